// round 16
// baseline (speedup 1.0000x reference)
#include <cuda_runtime.h>

// LIF forward: X[B=128, T=32, N=8192] fp32 -> spikes fp32 (same shape).
// Per (b, n): mem = mem + (x_t - mem)/2 ; spike = mem > 1 ; mem = 0 on spike.
//
// FINAL — locked after 15 rounds / 10 mechanisms probed.
//
// Touch-once 256 MiB stream (128 MiB read + 128 MiB write, ~3 flops/elem).
//   - scalar LDG/STG float4 (this kernel)          38.1-41.6 us
//   - 2-column per-thread MLP (63 regs)            40.1 us (occ loss)
//   - explicit 4-deep load batching                39.8 us (neutral)
//   - cp.async.bulk/TMA + mbarrier 8-stage ring    38.0 us (neutral)
//   - reg-capped single-wave residency (occ 74%)   38.2 us (neutral)
//   - streaming .cs loads/stores                   39.4 us (neutral)
//   - write-through .wt stores                     40.5 us (neutral)
//   - bitpacked read/write phase separation        42.6 / 90 us (regs/spill)
//   - TPB=128 granularity                          40.8 us (neutral)
//   - 256-bit ld/st.global.v8.f32 (occ 40%!)       39.7 us (neutral)
// Occupancy 40%..77%, issue 13%..34%, LSU instruction count halved — all
// land in one noise band = ~7.0 TB/s effective steady-state HBM throughput
// (88% of the 8 TB/s spec): the practical ceiling for an interleaved 50/50
// R/W touch-once stream. The DRAM subsystem is the binding resource; byte
// count and direction mix are fixed by the problem, so no kernel-side
// transformation can move the bound. Compute pipes idle (fma ~4%).
//
// Layout: 1 thread = 1 float4 column (4 consecutive n); walks t with
// stride N/4 -> every warp issues perfectly coalesced 128B transactions.
// Full T=32 unroll lets ptxas batch independent LDG.128s ahead of the
// serial 2-FMA-per-step recurrence chain. regs=39, occ ~63%.

static constexpr int B = 128;
static constexpr int T = 32;
static constexpr int N = 8192;
static constexpr int N4 = N / 4;          // float4 columns per plane
static constexpr int TOTAL4 = B * N4;     // 262144 float4 lanes
static constexpr int TPB = 256;

__device__ __forceinline__ float4 step4(float4& m, const float4 x) {
    // exact reference rounding: mem += (x - mem) * 0.5f
    m.x = m.x + (x.x - m.x) * 0.5f;
    m.y = m.y + (x.y - m.y) * 0.5f;
    m.z = m.z + (x.z - m.z) * 0.5f;
    m.w = m.w + (x.w - m.w) * 0.5f;
    float4 s;
    s.x = (m.x > 1.0f) ? 1.0f : 0.0f;
    s.y = (m.y > 1.0f) ? 1.0f : 0.0f;
    s.z = (m.z > 1.0f) ? 1.0f : 0.0f;
    s.w = (m.w > 1.0f) ? 1.0f : 0.0f;
    // hard reset to 0 where spiked
    if (s.x != 0.0f) m.x = 0.0f;
    if (s.y != 0.0f) m.y = 0.0f;
    if (s.z != 0.0f) m.z = 0.0f;
    if (s.w != 0.0f) m.w = 0.0f;
    return s;
}

__global__ __launch_bounds__(TPB) void lif_kernel(const float4* __restrict__ X,
                                                  float4* __restrict__ out) {
    int idx = blockIdx.x * TPB + threadIdx.x;  // 0 .. TOTAL4-1
    if (idx >= TOTAL4) return;

    int b = idx / N4;
    int n4 = idx - b * N4;

    const float4* xp = X + (size_t)b * T * N4 + n4;
    float4* op = out + (size_t)b * T * N4 + n4;

    float4 m = make_float4(0.f, 0.f, 0.f, 0.f);

#pragma unroll
    for (int t = 0; t < T; t++) {
        float4 x = xp[(size_t)t * N4];
        float4 s = step4(m, x);
        op[(size_t)t * N4] = s;
    }
}

extern "C" void kernel_launch(void* const* d_in, const int* in_sizes, int n_in,
                              void* d_out, int out_size) {
    const float4* X = (const float4*)d_in[0];
    float4* out = (float4*)d_out;
    lif_kernel<<<TOTAL4 / TPB, TPB>>>(X, out);
}